// round 16
// baseline (speedup 1.0000x reference)
#include <cuda_runtime.h>
#include <cstdint>

// Problem constants
#define NB   8
#define TPD  2048
#define ED   4096
#define TD   16384
#define VD   17
#define OUTROWS 131072
#define KSP  4              // K splits
#define KC   (ED / KSP)     // 1024 K per block
#define KT   32             // K floats per pipeline stage
#define NSTG (KC / KT)      // 32 stages
#define MTIL 128            // bucket rows per block
#define RMAX 16384

typedef unsigned long long ull;

// Scratch (device globals)
__device__ float g_WeffJ[64 * ED];      // [j=s0*8+s][e], tf32-rounded
__device__ float g_beff[8];             // includes b2
__device__ int   g_bucket[64 * 2048];   // [(n*8+s0)][slot] = (rank<<16)|tp
__device__ int   g_bcount[64];
__device__ int   g_count8[NB];          // 8 * per-batch masked count
__device__ float g_part[(size_t)KSP * NB * RMAX * 8];  // [ksp][n][rank][s], 16MB

// ---------------------------------------------------------------------------
// helpers
// ---------------------------------------------------------------------------
__device__ __forceinline__ void ldgsts16(void* dst, const void* src) {
    unsigned saddr = (unsigned)__cvta_generic_to_shared(dst);
    asm volatile("cp.async.cg.shared.global [%0], [%1], 16;\n" :: "r"(saddr), "l"(src));
}
__device__ __forceinline__ void cp_commit() {
    asm volatile("cp.async.commit_group;\n" ::: "memory");
}
template <int N>
__device__ __forceinline__ void cp_wait() {
    asm volatile("cp.async.wait_group %0;\n" :: "n"(N) : "memory");
}
__device__ __forceinline__ float to_tf32_rna(float f) {
    unsigned u;
    asm("cvt.rna.tf32.f32 %0, %1;" : "=r"(u) : "f"(f));
    return __uint_as_float(u);
}
// XOR-swizzled smem float index: 32-float (128B) rows, 16B chunk swizzle
__device__ __forceinline__ int aidx(int r, int ce) {
    return r * 32 + ((((ce >> 2) ^ (r & 7)) << 2) | (ce & 3));
}
__device__ __forceinline__ void mma_tf32(float* c, const unsigned* a,
                                         unsigned b0, unsigned b1) {
    asm volatile(
        "mma.sync.aligned.m16n8k8.row.col.f32.tf32.tf32.f32 "
        "{%0,%1,%2,%3}, {%4,%5,%6,%7}, {%8,%9}, {%0,%1,%2,%3};"
        : "+f"(c[0]), "+f"(c[1]), "+f"(c[2]), "+f"(c[3])
        : "r"(a[0]), "r"(a[1]), "r"(a[2]), "r"(a[3]), "r"(b0), "r"(b1));
}

// ---------------------------------------------------------------------------
// K01 fused, 1024 threads/block (R14-proven):
//   blocks [0,8): per-batch argmax + bucketed compaction; payload (rank<<16)|tp
//   blocks [8,264): WeffJ rows for 16 e-values each (+beff at block 8)
// ---------------------------------------------------------------------------
__global__ __launch_bounds__(1024) void k01(const float* __restrict__ W1,
                                            const float* __restrict__ W2,
                                            const float* __restrict__ b1,
                                            const float* __restrict__ b2,
                                            const int* __restrict__ value,
                                            const int* __restrict__ depth) {
    int bid = blockIdx.x;
    int tid = threadIdx.x;

    if (bid >= 8) {
        // ---- WeffJ: 16 e-values per block ----
        __shared__ __align__(16) float w2s[512];
        __shared__ __align__(16) float w1r[16][512];
        int e0 = (bid - 8) * 16;
        if (tid < 128) ((float4*)w2s)[tid] = ((const float4*)W2)[tid];
        ((float4*)&w1r[0][0])[tid]        = ((const float4*)(W1 + (size_t)e0 * 512))[tid];
        ((float4*)&w1r[0][0])[tid + 1024] = ((const float4*)(W1 + (size_t)e0 * 512))[tid + 1024];
        __syncthreads();
        int sub = tid >> 6;       // which e (0..15)
        int t64 = tid & 63;
        int s0 = t64 >> 3, s = t64 & 7;
        int e = e0 + sub;
        float acc = 0.f;
#pragma unroll
        for (int c = 0; c < 64; c++) acc += w1r[sub][c * 8 + s0] * w2s[c * 8 + s];
        g_WeffJ[(size_t)(s0 * 8 + s) * ED + e] = to_tf32_rna(acc);
        if (bid == 8 && tid < 8) {
            float a = 0.f;
#pragma unroll
            for (int c = 0; c < 64; c++) a += b1[c] * w2s[c * 8 + tid];
            g_beff[tid] = a + b2[0];
        }
    } else {
        // ---- prep: batch n, 1024 threads, coalesced int4, 4 passes ----
        int n = bid;
        const int* dep = depth + n * TD;
        const int* val = value + n * TD;
        __shared__ int s_idx;
        __shared__ int wsum[32];
        __shared__ ull wtA[32], wtB[32];
        __shared__ int wbase[32 * 8];
        __shared__ int sb_r;
        __shared__ int sb_s0[8];
        __shared__ int pass_tot;
        __shared__ int pass_tot_s0[8];

        int lane = tid & 31, wid = tid >> 5;  // 32 warps

        int maxv = dep[TD - 1];
        if (tid == 0) { s_idx = TD; sb_r = 0; }
        if (tid < 8) sb_s0[tid] = 0;
        __syncthreads();
        for (int t0 = tid * 4; t0 < TD; t0 += 4096) {
            int4 d = *(const int4*)(dep + t0);
            int prev = (t0 == 0) ? (maxv - 1) : dep[t0 - 1];
            if (d.x == maxv && prev < maxv) atomicMin(&s_idx, t0);
            if (d.y == maxv && d.x < maxv) atomicMin(&s_idx, t0 + 1);
            if (d.z == maxv && d.y < maxv) atomicMin(&s_idx, t0 + 2);
            if (d.w == maxv && d.z < maxv) atomicMin(&s_idx, t0 + 3);
        }
        __syncthreads();
        int idx = s_idx;
        int bb = n * 8;

        for (int pass = 0; pass < 4; pass++) {
            int t0 = pass * 4096 + tid * 4;
            int4 vv = *(const int4*)(val + t0);
            int vj[4] = {vv.x, vv.y, vv.z, vv.w};
            unsigned mb = 0;
            int cnt = 0;
            ull cA = 0, cB = 0;  // per-s0 counts, 16-bit fields (s0 0-3 / 4-7)
#pragma unroll
            for (int j = 0; j < 4; j++) {
                int t = t0 + j;
                bool m = (t < idx) && (vj[j] == 2);
                mb |= ((unsigned)m) << j;
                cnt += (int)m;
                if (m) {
                    int f = t & 7;
                    if (f < 4) cA += 1ull << (f * 16);
                    else       cB += 1ull << ((f - 4) * 16);
                }
            }
            int v = cnt;
            ull ciA = cA, ciB = cB;
#pragma unroll
            for (int o = 1; o < 32; o <<= 1) {
                int u  = __shfl_up_sync(0xffffffffu, v, o);
                ull uA = __shfl_up_sync(0xffffffffu, ciA, o);
                ull uB = __shfl_up_sync(0xffffffffu, ciB, o);
                if (lane >= o) { v += u; ciA += uA; ciB += uB; }
            }
            if (lane == 31) { wsum[wid] = v; wtA[wid] = ciA; wtB[wid] = ciB; }
            __syncthreads();
            if (wid == 0) {
                int w = wsum[lane];
                int wi = w;
#pragma unroll
                for (int o = 1; o < 32; o <<= 1) {
                    int u = __shfl_up_sync(0xffffffffu, wi, o);
                    if (lane >= o) wi += u;
                }
                wsum[lane] = wi - w;
                if (lane == 31) pass_tot = wi;
            } else if (wid == 1 && lane < 8) {
                int s0 = lane;
                int run = 0;
#pragma unroll
                for (int w = 0; w < 32; w++) {
                    int c = (s0 < 4) ? (int)((wtA[w] >> (s0 * 16)) & 0xFFFF)
                                     : (int)((wtB[w] >> ((s0 - 4) * 16)) & 0xFFFF);
                    wbase[w * 8 + s0] = run;
                    run += c;
                }
                pass_tot_s0[s0] = run;
            }
            __syncthreads();
            int r = sb_r + wsum[wid] + (v - cnt);
            ull exA = ciA - cA, exB = ciB - cB;
#pragma unroll
            for (int j = 0; j < 4; j++) {
                if ((mb >> j) & 1u) {
                    int t = t0 + j;
                    int s0 = t & 7;
                    int ex = (s0 < 4) ? (int)((exA >> (s0 * 16)) & 0xFFFF)
                                      : (int)((exB >> ((s0 - 4) * 16)) & 0xFFFF);
                    int slot = sb_s0[s0] + wbase[wid * 8 + s0] + ex;
                    g_bucket[(bb + s0) * 2048 + slot] = (r << 16) | (t >> 3);
                    if (s0 < 4) exA += 1ull << (s0 * 16);
                    else        exB += 1ull << ((s0 - 4) * 16);
                    r++;
                }
            }
            __syncthreads();
            if (tid == 0) sb_r += pass_tot;
            if (tid < 8) sb_s0[tid] += pass_tot_s0[tid];
            __syncthreads();
        }
        if (tid < 8) g_bcount[bb + tid] = sb_s0[tid];
        if (tid == 0) g_count8[n] = 8 * sb_r;
    }
}

// ---------------------------------------------------------------------------
// K3_BKT: bucketed tf32 mma GEMM with K-split.
//   Block (bx = rb*32 + ksp*8 + s0, n): rows = bucket[(n,s0)][rb*128, +128),
//   N = 8 (s of this s0), K chunk = ksp*1024..+1024, 32 KT=32 stages.
//   128 threads = 4 warps, warp tile m32n8 (R13-proven fragment pattern).
//   Partials -> g_part[ksp][n][rank][s].
// ---------------------------------------------------------------------------
__global__ __launch_bounds__(128) void k3_bkt(const float* __restrict__ x) {
    int bx = blockIdx.x;
    int s0 = bx & 7, ksp = (bx >> 3) & 3, rb = bx >> 5;
    int n = blockIdx.y;
    int bucket = n * 8 + s0;
    int bcnt = g_bcount[bucket];
    int row0 = rb * MTIL;
    if (row0 >= bcnt) return;
    int tid = threadIdx.x;
    int w = tid >> 5, lane = tid & 31;
    int gid = lane >> 2, tig = lane & 3;

    __shared__ __align__(16) float As[2][MTIL * 32];  // 32KB
    __shared__ __align__(16) float Bs[2][8 * 32];     // 2KB
    __shared__ int stp_s[MTIL];
    __shared__ int rk_s[MTIL];

    // prologue: row metadata (coalesced; one row per thread)
    {
        int gr = row0 + tid;
        if (gr < bcnt) {
            int p = g_bucket[bucket * 2048 + gr];
            rk_s[tid]  = p >> 16;
            stp_s[tid] = p & 0xFFFF;
        } else {
            rk_s[tid] = -1;
            stp_s[tid] = 0;
        }
    }
    __syncthreads();

    const float* xb = x + (size_t)n * TPD * ED + ksp * KC;
    const float* wb = g_WeffJ + (size_t)(s0 * 8) * ED + ksp * KC;

    // stage loader: A 128 rows x 8 chunks (8 lanes/row -> 128B coalesced),
    // B 8 rows x 8 chunks. XOR swizzle (R13-proven).
    auto load_stage = [&](int st, int b) {
        int kbase = st * KT;
#pragma unroll
        for (int p = 0; p < 8; p++) {
            int g = p * 128 + tid;
            int r = g >> 3, c = g & 7;
            ldgsts16(&As[b][r * 32 + ((c ^ (r & 7)) << 2)],
                     xb + (size_t)stp_s[r] * ED + kbase + c * 4);
        }
        if (tid < 64) {
            int r = tid >> 3, c = tid & 7;
            ldgsts16(&Bs[b][r * 32 + ((c ^ (r & 7)) << 2)],
                     wb + (size_t)r * ED + kbase + c * 4);
        }
        cp_commit();
    };

    load_stage(0, 0);

    float acc[2][4];
#pragma unroll
    for (int i = 0; i < 2; i++)
#pragma unroll
        for (int q = 0; q < 4; q++) acc[i][q] = 0.f;

    for (int st = 0; st < NSTG; st++) {
        int b = st & 1;
        if (st + 1 < NSTG) {
            load_stage(st + 1, b ^ 1);
            cp_wait<1>();
        } else {
            cp_wait<0>();
        }
        __syncthreads();

#pragma unroll
        for (int kk = 0; kk < 4; kk++) {
            int c0 = kk * 8 + tig;
            unsigned b0 = __float_as_uint(Bs[b][aidx(gid, c0)]);
            unsigned b1 = __float_as_uint(Bs[b][aidx(gid, c0 + 4)]);
#pragma unroll
            for (int i = 0; i < 2; i++) {
                int rl = w * 32 + i * 16 + gid;
                unsigned a[4];
                a[0] = __float_as_uint(As[b][aidx(rl, c0)]);
                a[1] = __float_as_uint(As[b][aidx(rl + 8, c0)]);
                a[2] = __float_as_uint(As[b][aidx(rl, c0 + 4)]);
                a[3] = __float_as_uint(As[b][aidx(rl + 8, c0 + 4)]);
                mma_tf32(acc[i], a, b0, b1);
            }
        }
        __syncthreads();
    }

    // store partials: lane (gid,tig) holds rows (m, m+8), cols (2tig, 2tig+1)
    float* pb = g_part + (size_t)(ksp * NB + n) * RMAX * 8;
#pragma unroll
    for (int i = 0; i < 2; i++) {
        int m = w * 32 + i * 16 + gid;
        int r1 = rk_s[m], r2 = rk_s[m + 8];
        if (r1 >= 0)
            *(float2*)(pb + (size_t)r1 * 8 + 2 * tig) = make_float2(acc[i][0], acc[i][1]);
        if (r2 >= 0)
            *(float2*)(pb + (size_t)r2 * 8 + 2 * tig) = make_float2(acc[i][2], acc[i][3]);
    }
}

// ---------------------------------------------------------------------------
// K4: fused epilogue + default fill (R8-proven). Strip of 256 output rows.
// Heavy rows (j < count8): y2 = sum_ksp part[j] + beff[s]; tail: y2 = b2.
// ---------------------------------------------------------------------------
__global__ __launch_bounds__(256) void k4_epi(const float* __restrict__ W3,
                                              const float* __restrict__ b2,
                                              float* __restrict__ out) {
    int n = blockIdx.y;
    int j0 = blockIdx.x * 256;
    int tid = threadIdx.x;
    __shared__ float y2s[256];
    __shared__ float w3s[VD];
    __shared__ float beffs[8];
    if (tid < VD) w3s[tid] = W3[tid];
    if (tid < 8) beffs[tid] = g_beff[tid];
    __syncthreads();

    int count8 = g_count8[n];
    int j = j0 + tid;
    float acc;
    if (j < count8) {
        acc = beffs[j & 7];
#pragma unroll
        for (int ksi = 0; ksi < KSP; ksi++)
            acc += g_part[(size_t)(ksi * NB + n) * (RMAX * 8) + j];
    } else {
        acc = b2[0];
    }
    y2s[tid] = acc;
    __syncthreads();

    float* ob = out + ((size_t)n * OUTROWS + j0) * VD;
    const int NF4 = 256 * VD / 4;  // 1088
    for (int f = tid; f < NF4; f += 256) {
        float4 o;
#pragma unroll
        for (int c = 0; c < 4; c++) {
            int idx = f * 4 + c;
            int jj = idx / VD;
            int vv = idx - jj * VD;
            ((float*)&o)[c] = y2s[jj] * w3s[vv];
        }
        *(float4*)(ob + f * 4) = o;
    }
}

// ---------------------------------------------------------------------------
extern "C" void kernel_launch(void* const* d_in, const int* in_sizes, int n_in,
                              void* d_out, int out_size) {
    const float* x     = (const float*)d_in[0];
    const int*   value = (const int*)d_in[1];   // jax x64-off: int32
    const int*   depth = (const int*)d_in[2];
    // d_in[3] = pos, unused
    const float* W1    = (const float*)d_in[4];
    const float* b1    = (const float*)d_in[5];
    const float* W2    = (const float*)d_in[6];
    const float* b2    = (const float*)d_in[7];
    const float* W3    = (const float*)d_in[8];
    float* out = (float*)d_out;

    k01<<<264, 1024>>>(W1, W2, b1, b2, value, depth);
    k3_bkt<<<dim3(16 * 32, NB), 128>>>(x);   // rb(16) x ksp(4) x s0(8)
    k4_epi<<<dim3(OUTROWS / 256, NB), 256>>>(W3, b2, out);
}